// round 15
// baseline (speedup 1.0000x reference)
#include <cuda_runtime.h>
#include <math.h>
#include <stdint.h>

// Problem constants
#define Bsz 8
#define Ssz 512
#define Dsz 768
#define Hsz 12
#define DHsz 64
#define FFsz 3072
#define MROWS (Bsz*Ssz)   // 4096

// ---------------------------------------------------------------------------
// Scratch (single static __device__ f32 array; no allocations anywhere)
// qn kn qb kb vb x1 xn xr ctx x2 (10 MD) + hid (MF) + 6 DxD weightsT + 2 big weightsT + L
#define MDsz ((size_t)MROWS*Dsz)
#define MFsz ((size_t)MROWS*FFsz)
#define DDsz ((size_t)Dsz*Dsz)
#define DFsz ((size_t)Dsz*FFsz)
#define F32_SCR (10*MDsz + MFsz + 6*DDsz + 2*DFsz + Bsz*Ssz)
static __device__ float g_f32[F32_SCR];
static __device__ unsigned char g_mask[Bsz*Ssz];
static __device__ int g_mask_is_int;

// ---------------------------------------------------------------------------
__device__ __forceinline__ uint32_t smem_u32(const void* p) {
    uint32_t a;
    asm("{ .reg .u64 t; cvta.to.shared.u64 t, %1; cvt.u32.u64 %0, t; }" : "=r"(a) : "l"(p));
    return a;
}
__device__ __forceinline__ float to_tf32(float x) {
    uint32_t u;
    asm("cvt.rna.tf32.f32 %0, %1;" : "=r"(u) : "f"(x));
    return __uint_as_float(u);
}
__device__ __forceinline__ void cp_async16(uint32_t saddr, const void* gptr) {
    asm volatile("cp.async.cg.shared.global [%0], [%1], 16;\n" :: "r"(saddr), "l"(gptr));
}
__device__ __forceinline__ void cp_commit() { asm volatile("cp.async.commit_group;\n"); }
__device__ __forceinline__ void cp_wait0() { asm volatile("cp.async.wait_group 0;\n"); }

__device__ __forceinline__ void ldsm_x4(uint32_t* r, uint32_t addr) {
    asm volatile("ldmatrix.sync.aligned.m8n8.x4.shared.b16 {%0,%1,%2,%3}, [%4];"
                 : "=r"(r[0]), "=r"(r[1]), "=r"(r[2]), "=r"(r[3]) : "r"(addr));
}
__device__ __forceinline__ void mma_tf32(float* c, const uint32_t* a, const uint32_t* b) {
    asm volatile(
        "mma.sync.aligned.m16n8k8.row.col.f32.tf32.tf32.f32 "
        "{%0,%1,%2,%3}, {%4,%5,%6,%7}, {%8,%9}, {%0,%1,%2,%3};\n"
        : "+f"(c[0]), "+f"(c[1]), "+f"(c[2]), "+f"(c[3])
        : "r"(a[0]), "r"(a[1]), "r"(a[2]), "r"(a[3]), "r"(b[0]), "r"(b[1]));
}

// ---------------------------------------------------------------------------
// tf32 single-pass GEMM with ldmatrix fragment loads.
// Inputs are rna-pre-rounded f32 (producers); HMMA truncation is then lossless.
// Y[M,N] = A[M,K] @ B[N,K]^T + bias.  fuse: 0 f32; 1 relu+round; 2 +res.
// CTA 128x128, BK=32, 256 thr (8 warps), warp tile 64x32.
// smem: 2 buffers x (A|B), each tile 128 rows x 128B, chunk-XOR swizzled.
#define G_TILE 16384
#define G_BUF  32768
#define G_SMEM 65536

struct GemmArgs { const float *A, *B, *bias, *res; float* Y; };
struct GemmBatch { GemmArgs a[3]; };

__global__ __launch_bounds__(256) void gemm_tf32_ldsm_kernel(
    GemmBatch gb, int M, int N, int K, int fuse)
{
    const GemmArgs ga = gb.a[blockIdx.z];
    extern __shared__ unsigned char dsm[];
    const uint32_t sbase = smem_u32(dsm);

    const int tid = threadIdx.x, wid = tid >> 5, lane = tid & 31;
    const int gID = lane >> 2, tig = lane & 3;
    const int warp_m = (wid & 1) * 64, warp_n = (wid >> 1) * 32;
    const int m0 = blockIdx.y * 128, n0 = blockIdx.x * 128;

    // ldmatrix per-lane addressing: quadrant q supplies matrix q's row addrs
    const int q = lane >> 3, lrow = lane & 7;
    const int rowOff = ((q >> 1) << 3) + lrow;   // 0..15 within a 16-row tile
    const int half   = q & 1;                    // k-half 0/1

    float acc[4][4][4];
    #pragma unroll
    for (int i = 0; i < 4; i++)
        #pragma unroll
        for (int j = 0; j < 4; j++)
            #pragma unroll
            for (int c = 0; c < 4; c++) acc[i][j][c] = 0.0f;

    // stage K-slab kt (32 f32) into buffer buf: 2048 16B chunks, 8 per thread
    auto stage = [&](int kt, int buf) {
        #pragma unroll
        for (int i = 0; i < 8; i++) {
            const int id  = tid + (i << 8);
            const int arr = id >> 10;           // 0:A 1:B
            const int row = (id >> 3) & 127;
            const int c   = id & 7;
            const float* g = arr ? ga.B : ga.A;
            const int grow = (arr ? n0 : m0) + row;
            cp_async16(sbase + (uint32_t)buf * G_BUF + (uint32_t)arr * G_TILE
                           + (uint32_t)row * 128 + (uint32_t)((c ^ (row & 7)) << 4),
                       g + (size_t)grow * K + kt * 32 + c * 4);
        }
    };

    const int nk = K / 32;
    stage(0, 0);
    cp_commit();

    for (int kt = 0; kt < nk; kt++) {
        const int buf = kt & 1;
        cp_wait0();
        __syncthreads();
        if (kt + 1 < nk) { stage(kt + 1, buf ^ 1); cp_commit(); }

        const uint32_t bb = sbase + (uint32_t)buf * G_BUF;
        #pragma unroll
        for (int kkg = 0; kkg < 4; kkg++) {
            const int c0 = (kkg << 1) + half;    // 16B chunk index (lane-dep)
            uint32_t Bf[4][2];
            #pragma unroll
            for (int pr = 0; pr < 2; pr++) {
                const int Rb = warp_n + pr * 16 + rowOff;
                uint32_t t[4];
                ldsm_x4(t, bb + G_TILE + (uint32_t)Rb * 128
                             + (uint32_t)((c0 ^ (Rb & 7)) << 4));
                Bf[pr*2][0] = t[0]; Bf[pr*2][1] = t[1];
                Bf[pr*2+1][0] = t[2]; Bf[pr*2+1][1] = t[3];
            }
            #pragma unroll
            for (int mt = 0; mt < 4; mt++) {
                const int Ra = warp_m + mt * 16 + rowOff;
                uint32_t t[4];
                ldsm_x4(t, bb + (uint32_t)Ra * 128
                             + (uint32_t)((c0 ^ (Ra & 7)) << 4));
                uint32_t af[4] = { t[0], t[2], t[1], t[3] };   // {a0,a1,a2,a3}
                #pragma unroll
                for (int nt = 0; nt < 4; nt++)
                    mma_tf32(acc[mt][nt], af, Bf[nt]);
            }
        }
    }

    // epilogue (D: c0,c1 row m cols 2tig..; c2,c3 row m+8)
    #pragma unroll
    for (int mt = 0; mt < 4; mt++) {
        const int m = m0 + warp_m + mt * 16 + gID;
        #pragma unroll
        for (int nt = 0; nt < 4; nt++) {
            const int n = n0 + warp_n + nt * 8 + 2 * tig;
            const float* c = acc[mt][nt];
            const float bv0 = ga.bias[n], bv1 = ga.bias[n + 1];
            float v00 = c[0] + bv0, v01 = c[1] + bv1;
            float v10 = c[2] + bv0, v11 = c[3] + bv1;
            if (fuse == 1) {
                v00 = to_tf32(fmaxf(v00, 0.0f)); v01 = to_tf32(fmaxf(v01, 0.0f));
                v10 = to_tf32(fmaxf(v10, 0.0f)); v11 = to_tf32(fmaxf(v11, 0.0f));
            } else if (fuse == 2) {
                float2 r0 = *(const float2*)(ga.res + (size_t)m * N + n);
                float2 r1 = *(const float2*)(ga.res + (size_t)(m + 8) * N + n);
                v00 += r0.x; v01 += r0.y; v10 += r1.x; v11 += r1.y;
            }
            *(float2*)(ga.Y + (size_t)m * N + n)       = make_float2(v00, v01);
            *(float2*)(ga.Y + (size_t)(m + 8) * N + n) = make_float2(v10, v11);
        }
    }
}

// ---------------------------------------------------------------------------
// Weight prep: W [K,N] f32 -> WT [N,K] f32 rna-rounded
__global__ __launch_bounds__(256) void transpose_round_kernel(
    const float* __restrict__ W, float* __restrict__ T, int K, int N)
{
    __shared__ float t[32][33];
    const int tx = threadIdx.x, ty = threadIdx.y;
    const int n0 = blockIdx.x * 32, k0 = blockIdx.y * 32;
    #pragma unroll
    for (int j = ty; j < 32; j += 8)
        t[j][tx] = W[(size_t)(k0 + j) * N + n0 + tx];
    __syncthreads();
    #pragma unroll
    for (int j = ty; j < 32; j += 8)
        T[(size_t)(n0 + j) * K + k0 + tx] = to_tf32(t[tx][j]);
}

// Elementwise rna round
__global__ void round_kernel(const float* __restrict__ X, float* __restrict__ Y, int n)
{
    int i = blockIdx.x * 256 + threadIdx.x;
    if (i < n) Y[i] = to_tf32(X[i]);
}

// ---------------------------------------------------------------------------
// LayerNorm over last dim (768); rna-rounded output (feeds GEMMs only).
__global__ __launch_bounds__(256) void layernorm_round_kernel(
    const float* __restrict__ X, const float* __restrict__ g,
    const float* __restrict__ be, float* __restrict__ Y)
{
    __shared__ float red[256];
    __shared__ float s_mean, s_inv;
    const int row = blockIdx.x, tid = threadIdx.x;
    const float* x = X + (size_t)row * Dsz;

    float s = 0.0f;
    for (int i = tid; i < Dsz; i += 256) s += x[i];
    red[tid] = s; __syncthreads();
    for (int o = 128; o > 0; o >>= 1) { if (tid < o) red[tid] += red[tid + o]; __syncthreads(); }
    if (tid == 0) s_mean = red[0] * (1.0f / Dsz);
    __syncthreads();
    const float m = s_mean;

    float v = 0.0f;
    for (int i = tid; i < Dsz; i += 256) { float d = x[i] - m; v += d * d; }
    red[tid] = v; __syncthreads();
    for (int o = 128; o > 0; o >>= 1) { if (tid < o) red[tid] += red[tid + o]; __syncthreads(); }
    if (tid == 0) s_inv = rsqrtf(red[0] * (1.0f / Dsz) + 1e-5f);
    __syncthreads();
    const float inv = s_inv;

    for (int i = tid; i < Dsz; i += 256)
        Y[(size_t)row * Dsz + i] = to_tf32((x[i] - m) * inv * g[i] + be[i]);
}

// ---------------------------------------------------------------------------
// Neighbor affinity (f32 qn/kn)
__global__ __launch_bounds__(128) void affinity_kernel(
    const float* __restrict__ qn, const float* __restrict__ kn,
    const float* __restrict__ prev, const int* __restrict__ lidx,
    float* __restrict__ a_out)
{
    const int t = blockIdx.x, b = blockIdx.y, tid = threadIdx.x;
    const float* q0 = qn + ((size_t)b * Ssz + t) * Dsz;
    const float* q1 = q0 + Dsz;
    const float* k0 = kn + ((size_t)b * Ssz + t) * Dsz;
    const float* k1 = k0 + Dsz;
    float sf = 0.0f, sb = 0.0f;
    for (int i = tid; i < Dsz; i += 128) { sf += q0[i] * k1[i]; sb += q1[i] * k0[i]; }
    __shared__ float rf[128], rb[128];
    rf[tid] = sf; rb[tid] = sb; __syncthreads();
    for (int o = 64; o > 0; o >>= 1) {
        if (tid < o) { rf[tid] += rf[tid + o]; rb[tid] += rb[tid + o]; }
        __syncthreads();
    }
    if (tid == 0) {
        float f = rf[0] * (1.0f / 64.0f), bw = rb[0] * (1.0f / 64.0f);
        float ah = 0.5f * (1.0f / (1.0f + expf(-f)) + 1.0f / (1.0f + expf(-bw)));
        float a;
        if (*lidx == 0) a = ah;
        else { float p = prev[(size_t)b * (Ssz - 1) + t]; a = p + (1.0f - p) * ah; }
        a_out[(size_t)b * (Ssz - 1) + t] = a;
    }
}

// L[b,0]=0; L[b,k]=sum_{t<k} log(a[b,t])
__global__ void scan_kernel(const float* __restrict__ a, float* __restrict__ Lout)
{
    const int b = blockIdx.x;
    if (threadIdx.x == 0) {
        float acc = 0.0f;
        Lout[(size_t)b * Ssz] = 0.0f;
        for (int t = 0; t < Ssz - 1; t++) {
            acc += logf(a[(size_t)b * (Ssz - 1) + t]);
            Lout[(size_t)b * Ssz + t + 1] = acc;
        }
    }
}

// ---------------------------------------------------------------------------
// Mask dtype handling
__global__ void mask_detect_kernel(const unsigned char* __restrict__ m)
{
    if (threadIdx.x == 0)
        g_mask_is_int = (m[1] == 0 && m[2] == 0 && m[3] == 0) ? 1 : 0;
}
__global__ void mask_norm_kernel(const void* __restrict__ m)
{
    int i = blockIdx.x * 256 + threadIdx.x;
    if (i < Bsz * Ssz) {
        int v = g_mask_is_int ? ((const int*)m)[i] : (int)((const unsigned char*)m)[i];
        g_mask[i] = v ? 1 : 0;
    }
}

// ---------------------------------------------------------------------------
// Fused attention; ctx written rna-rounded f32 (feeds Wo GEMM)
#define ATT_SC 0
#define ATT_QS 16512
#define ATT_KT 18592
#define ATT_LS 26912
#define ATT_MS 27424
#define ATT_SMEM_BYTES ((ATT_MS + 128) * 4)

__global__ __launch_bounds__(256) void attn_fused_kernel(
    const float* __restrict__ gq, const float* __restrict__ gk,
    const float* __restrict__ gv, const float* __restrict__ Lg,
    float* __restrict__ attnh, float* __restrict__ ctx)
{
    extern __shared__ float sm[];
    float* Sc = sm + ATT_SC;
    float* qs = sm + ATT_QS;
    float* kt = sm + ATT_KT;
    float* Ls = sm + ATT_LS;
    unsigned char* ms = (unsigned char*)(sm + ATT_MS);

    const int tid = threadIdx.x;
    const int bh = blockIdx.y, b = bh / Hsz, h = bh % Hsz;
    const int q0 = blockIdx.x * 32;

    for (int i = tid; i < Ssz; i += 256) {
        Ls[i] = Lg[(size_t)b * Ssz + i];
        ms[i] = g_mask[(size_t)b * Ssz + i];
    }
    {
        int r = tid >> 3, d8 = (tid & 7) << 3;
        const float* src = gq + ((size_t)b * Ssz + q0 + r) * Dsz + h * DHsz + d8;
        float* dst = qs + r * 65 + d8;
        #pragma unroll
        for (int u = 0; u < 8; u++) dst[u] = src[u];
    }
    __syncthreads();

    const int qg = tid >> 5;
    const int kg = tid & 31;

    for (int t = 0; t < 4; t++) {
        const int k0 = t * 128;
        {
            int krow = tid >> 1, dd = (tid & 1) << 5;
            const float* src = gk + ((size_t)b * Ssz + k0 + krow) * Dsz + h * DHsz + dd;
            float* dst = kt + krow * 65 + dd;
            #pragma unroll
            for (int u = 0; u < 32; u++) dst[u] = src[u];
        }
        __syncthreads();
        float acc[4][4] = {};
        #pragma unroll 4
        for (int dh = 0; dh < DHsz; dh++) {
            float qv[4], kv[4];
            #pragma unroll
            for (int i = 0; i < 4; i++) qv[i] = qs[(qg * 4 + i) * 65 + dh];
            #pragma unroll
            for (int j = 0; j < 4; j++) kv[j] = kt[(kg + 32 * j) * 65 + dh];
            #pragma unroll
            for (int i = 0; i < 4; i++)
                #pragma unroll
                for (int j = 0; j < 4; j++) acc[i][j] += qv[i] * kv[j];
        }
        #pragma unroll
        for (int i = 0; i < 4; i++)
            #pragma unroll
            for (int j = 0; j < 4; j++) {
                int kgl = k0 + kg + 32 * j;
                float vv = acc[i][j] * 0.125f;
                if (!ms[kgl]) vv = -1e9f;
                Sc[(qg * 4 + i) * 516 + kgl] = vv;
            }
        __syncthreads();
    }

    {
        const int row = tid >> 3, l8 = tid & 7;
        float* sr = Sc + row * 516;
        float mx = -1e30f;
        #pragma unroll 8
        for (int i = 0; i < 64; i++) mx = fmaxf(mx, sr[l8 + 8 * i]);
        for (int o = 1; o < 8; o <<= 1) mx = fmaxf(mx, __shfl_xor_sync(0xffffffffu, mx, o));
        float sum = 0.0f;
        #pragma unroll 8
        for (int i = 0; i < 64; i++) {
            int k = l8 + 8 * i;
            float e = __expf(sr[k] - mx);
            sr[k] = e; sum += e;
        }
        for (int o = 1; o < 8; o <<= 1) sum += __shfl_xor_sync(0xffffffffu, sum, o);
        const float inv = 1.0f / sum;
        const int qi = q0 + row;
        const float Lq = Ls[qi];
        #pragma unroll 8
        for (int i = 0; i < 64; i++) {
            int k = l8 + 8 * i;
            float Lk = Ls[k];
            float c = (qi >= k) ? __expf(Lq - Lk) : __expf(Lk - Lq);
            sr[k] = sr[k] * inv * c;
        }
    }
    __syncthreads();

    {
        float* dst = attnh + (size_t)bh * Ssz * Ssz + (size_t)q0 * Ssz;
        for (int idx = tid; idx < 32 * 512; idx += 256) {
            int r = idx >> 9, k = idx & 511;
            dst[(size_t)r * Ssz + k] = Sc[r * 516 + k];
        }
    }

    float oacc[2][4] = {};
    const int r0 = (tid >> 4) << 1;
    const int c0 = (tid & 15) << 2;
    for (int t = 0; t < 4; t++) {
        const int k0 = t * 128;
        __syncthreads();
        {
            int krow = tid >> 1, dd = (tid & 1) << 5;
            const float* src = gv + ((size_t)b * Ssz + k0 + krow) * Dsz + h * DHsz + dd;
            float* dst = kt + krow * 65 + dd;
            #pragma unroll
            for (int u = 0; u < 32; u++) dst[u] = src[u];
        }
        __syncthreads();
        #pragma unroll 4
        for (int kk = 0; kk < 128; kk++) {
            float a0 = Sc[r0 * 516 + k0 + kk];
            float a1 = Sc[(r0 + 1) * 516 + k0 + kk];
            const float* vr = kt + kk * 65 + c0;
            #pragma unroll
            for (int j = 0; j < 4; j++) { float bv = vr[j]; oacc[0][j] += a0 * bv; oacc[1][j] += a1 * bv; }
        }
    }
    #pragma unroll
    for (int rr = 0; rr < 2; rr++) {
        float4 o4 = make_float4(to_tf32(oacc[rr][0]), to_tf32(oacc[rr][1]),
                                to_tf32(oacc[rr][2]), to_tf32(oacc[rr][3]));
        *(float4*)(ctx + ((size_t)b * Ssz + q0 + r0 + rr) * Dsz + h * DHsz + c0) = o4;
    }
}

// ---------------------------------------------------------------------------
extern "C" void kernel_launch(void* const* d_in, const int* in_sizes, int n_in,
                              void* d_out, int out_size)
{
    (void)in_sizes; (void)n_in; (void)out_size;
    const float* x    = (const float*)d_in[0];
    const void*  mask = d_in[1];
    const float* prev = (const float*)d_in[2];
    const float* Wqn  = (const float*)d_in[3];  const float* bqn = (const float*)d_in[4];
    const float* Wkn  = (const float*)d_in[5];  const float* bkn = (const float*)d_in[6];
    const float* Wq   = (const float*)d_in[7];  const float* bq  = (const float*)d_in[8];
    const float* Wk   = (const float*)d_in[9];  const float* bk  = (const float*)d_in[10];
    const float* Wv   = (const float*)d_in[11]; const float* bv  = (const float*)d_in[12];
    const float* Wo   = (const float*)d_in[13]; const float* bo  = (const float*)d_in[14];
    const float* W1   = (const float*)d_in[15]; const float* b1  = (const float*)d_in[16];
    const float* W2   = (const float*)d_in[17]; const float* b2  = (const float*)d_in[18];
    const float* g1   = (const float*)d_in[19]; const float* be1 = (const float*)d_in[20];
    const float* g2   = (const float*)d_in[21]; const float* be2 = (const float*)d_in[22];
    const int*   lidx = (const int*)d_in[23];

    float* out_p   = (float*)d_out;
    float* a_p     = out_p + MDsz;
    float* attnh_p = a_p + (size_t)Bsz * (Ssz - 1);

    void* basep = nullptr;
    cudaGetSymbolAddress(&basep, g_f32);
    float* p = (float*)basep;
    float *qn = p;            p += MDsz;
    float *kn = p;            p += MDsz;
    float *qb = p;            p += MDsz;
    float *kb = p;            p += MDsz;
    float *vb = p;            p += MDsz;
    float *x1 = p;            p += MDsz;
    float *xn = p;            p += MDsz;
    float *xr = p;            p += MDsz;
    float *ctx = p;           p += MDsz;
    float *x2 = p;            p += MDsz;
    float *hid = p;           p += MFsz;
    float *WqnT = p;          p += DDsz;
    float *WknT = p;          p += DDsz;
    float *WqT = p;           p += DDsz;
    float *WkT = p;           p += DDsz;
    float *WvT = p;           p += DDsz;
    float *WoT = p;           p += DDsz;
    float *W1T = p;           p += DFsz;
    float *W2T = p;           p += DFsz;
    float *Lb = p;

    cudaFuncSetAttribute(attn_fused_kernel,
                         cudaFuncAttributeMaxDynamicSharedMemorySize, ATT_SMEM_BYTES);
    cudaFuncSetAttribute(gemm_tf32_ldsm_kernel,
                         cudaFuncAttributeMaxDynamicSharedMemorySize, G_SMEM);

    const dim3 tb(32, 8);
    const dim3 tD(Dsz / 32, Dsz / 32);
    const dim3 t1(FFsz / 32, Dsz / 32);     // W1 [D,FF] -> [FF,D]
    const dim3 t2(Dsz / 32, FFsz / 32);     // W2 [FF,D] -> [D,FF]

    // 1-3: QKV weights  4: LN1  5: round x  6: QKV GEMM (profiled slot)
    transpose_round_kernel<<<tD, tb>>>(Wq, WqT, Dsz, Dsz);
    transpose_round_kernel<<<tD, tb>>>(Wk, WkT, Dsz, Dsz);
    transpose_round_kernel<<<tD, tb>>>(Wv, WvT, Dsz, Dsz);
    layernorm_round_kernel<<<MROWS, 256>>>(x, g1, be1, xn);
    round_kernel<<<(int)((MDsz + 255) / 256), 256>>>(x, xr, (int)MDsz);
    {
        GemmBatch gbat;
        gbat.a[0] = { xn, WqT, bq, nullptr, qb };
        gbat.a[1] = { xn, WkT, bk, nullptr, kb };
        gbat.a[2] = { xn, WvT, bv, nullptr, vb };
        gemm_tf32_ldsm_kernel<<<dim3(Dsz / 128, MROWS / 128, 3), 256, G_SMEM>>>(
            gbat, MROWS, Dsz, Dsz, 0);
    }
    // rest of weight prep
    transpose_round_kernel<<<tD, tb>>>(Wqn, WqnT, Dsz, Dsz);
    transpose_round_kernel<<<tD, tb>>>(Wkn, WknT, Dsz, Dsz);
    transpose_round_kernel<<<tD, tb>>>(Wo, WoT, Dsz, Dsz);
    transpose_round_kernel<<<t1, tb>>>(W1, W1T, Dsz, FFsz);
    transpose_round_kernel<<<t2, tb>>>(W2, W2T, FFsz, Dsz);
    mask_detect_kernel<<<1, 32>>>((const unsigned char*)mask);
    mask_norm_kernel<<<16, 256>>>(mask);

    // affinity path
    {
        GemmBatch gbat;
        gbat.a[0] = { xr, WqnT, bqn, nullptr, qn };
        gbat.a[1] = { xr, WknT, bkn, nullptr, kn };
        gbat.a[2] = gbat.a[0];
        gemm_tf32_ldsm_kernel<<<dim3(Dsz / 128, MROWS / 128, 2), 256, G_SMEM>>>(
            gbat, MROWS, Dsz, Dsz, 0);
    }
    affinity_kernel<<<dim3(Ssz - 1, Bsz), 128>>>(qn, kn, prev, lidx, a_p);
    scan_kernel<<<Bsz, 32>>>(a_p, Lb);

    // attention
    attn_fused_kernel<<<dim3(Ssz / 32, Bsz * Hsz), 256, ATT_SMEM_BYTES>>>(
        qb, kb, vb, Lb, attnh_p, ctx);

    // output proj + residual -> x1
    {
        GemmBatch gbat;
        gbat.a[0] = { ctx, WoT, bo, x, x1 };
        gbat.a[1] = gbat.a[0]; gbat.a[2] = gbat.a[0];
        gemm_tf32_ldsm_kernel<<<dim3(Dsz / 128, MROWS / 128, 1), 256, G_SMEM>>>(
            gbat, MROWS, Dsz, Dsz, 2);
    }
    layernorm_round_kernel<<<MROWS, 256>>>(x1, g2, be2, x2);
    // FFN1: relu + round
    {
        GemmBatch gbat;
        gbat.a[0] = { x2, W1T, b1, nullptr, hid };
        gbat.a[1] = gbat.a[0]; gbat.a[2] = gbat.a[0];
        gemm_tf32_ldsm_kernel<<<dim3(FFsz / 128, MROWS / 128, 1), 256, G_SMEM>>>(
            gbat, MROWS, FFsz, Dsz, 1);
    }
    // FFN2: + residual x1 -> out
    {
        GemmBatch gbat;
        gbat.a[0] = { hid, W2T, b2, x1, out_p };
        gbat.a[1] = gbat.a[0]; gbat.a[2] = gbat.a[0];
        gemm_tf32_ldsm_kernel<<<dim3(Dsz / 128, MROWS / 128, 1), 256, G_SMEM>>>(
            gbat, MROWS, Dsz, FFsz, 2);
    }
}

// round 16
// speedup vs baseline: 1.1099x; 1.1099x over previous
#include <cuda_runtime.h>
#include <math.h>
#include <stdint.h>

// Problem constants
#define Bsz 8
#define Ssz 512
#define Dsz 768
#define Hsz 12
#define DHsz 64
#define FFsz 3072
#define MROWS (Bsz*Ssz)   // 4096

// ---------------------------------------------------------------------------
// Scratch (single static __device__ f32 array; no allocations anywhere)
#define MDsz ((size_t)MROWS*Dsz)
#define MFsz ((size_t)MROWS*FFsz)
#define DDsz ((size_t)Dsz*Dsz)
#define DFsz ((size_t)Dsz*FFsz)
#define F32_SCR (10*MDsz + MFsz + 6*DDsz + 2*DFsz + Bsz*Ssz)
static __device__ float g_f32[F32_SCR];
static __device__ unsigned char g_mask[Bsz*Ssz];
static __device__ int g_mask_is_int;

// ---------------------------------------------------------------------------
__device__ __forceinline__ uint32_t smem_u32(const void* p) {
    uint32_t a;
    asm("{ .reg .u64 t; cvta.to.shared.u64 t, %1; cvt.u32.u64 %0, t; }" : "=r"(a) : "l"(p));
    return a;
}
__device__ __forceinline__ float to_tf32(float x) {
    uint32_t u;
    asm("cvt.rna.tf32.f32 %0, %1;" : "=r"(u) : "f"(x));
    return __uint_as_float(u);
}
__device__ __forceinline__ void cp_async16(uint32_t saddr, const void* gptr) {
    asm volatile("cp.async.cg.shared.global [%0], [%1], 16;\n" :: "r"(saddr), "l"(gptr));
}
__device__ __forceinline__ void cp_commit() { asm volatile("cp.async.commit_group;\n"); }
__device__ __forceinline__ void cp_wait0() { asm volatile("cp.async.wait_group 0;\n"); }
__device__ __forceinline__ void cp_wait1() { asm volatile("cp.async.wait_group 1;\n"); }

__device__ __forceinline__ void ldsm_x4(uint32_t* r, uint32_t addr) {
    asm volatile("ldmatrix.sync.aligned.m8n8.x4.shared.b16 {%0,%1,%2,%3}, [%4];"
                 : "=r"(r[0]), "=r"(r[1]), "=r"(r[2]), "=r"(r[3]) : "r"(addr));
}
__device__ __forceinline__ void mma_tf32(float* c, const uint32_t* a, const uint32_t* b) {
    asm volatile(
        "mma.sync.aligned.m16n8k8.row.col.f32.tf32.tf32.f32 "
        "{%0,%1,%2,%3}, {%4,%5,%6,%7}, {%8,%9}, {%0,%1,%2,%3};\n"
        : "+f"(c[0]), "+f"(c[1]), "+f"(c[2]), "+f"(c[3])
        : "r"(a[0]), "r"(a[1]), "r"(a[2]), "r"(a[3]), "r"(b[0]), "r"(b[1]));
}

// ---------------------------------------------------------------------------
// tf32 single-pass GEMM, ldmatrix frag loads, 3-stage cp.async ring.
// Inputs rna-pre-rounded f32 (producers); HMMA truncation then lossless.
// Y[M,N] = A[M,K] @ B[N,K]^T + bias.  fuse: 0 f32; 1 relu+round; 2 +res.
// CTA 128x128, BK=32, 256 thr (8 warps), warp tile 64x32, 2 CTAs/SM.
#define G_TILE  16384
#define G_STAGE 32768
#define G_SMEM  (3*G_STAGE)    // 98304

struct GemmArgs { const float *A, *B, *bias, *res; float* Y; };
struct GemmBatch { GemmArgs a[3]; };

__global__ __launch_bounds__(256, 2) void gemm_tf32_ldsm_kernel(
    GemmBatch gb, int M, int N, int K, int fuse)
{
    const GemmArgs ga = gb.a[blockIdx.z];
    extern __shared__ unsigned char dsm[];
    const uint32_t sbase = smem_u32(dsm);

    const int tid = threadIdx.x, wid = tid >> 5, lane = tid & 31;
    const int gID = lane >> 2, tig = lane & 3;
    const int warp_m = (wid & 1) * 64, warp_n = (wid >> 1) * 32;
    const int m0 = blockIdx.y * 128, n0 = blockIdx.x * 128;

    // ldmatrix per-lane addressing: quadrant q supplies matrix q's row addrs
    const int q = lane >> 3, lrow = lane & 7;
    const int rowOff = ((q >> 1) << 3) + lrow;   // 0..15 within a 16-row tile
    const int half   = q & 1;                    // k-half 0/1

    float acc[4][4][4];
    #pragma unroll
    for (int i = 0; i < 4; i++)
        #pragma unroll
        for (int j = 0; j < 4; j++)
            #pragma unroll
            for (int c = 0; c < 4; c++) acc[i][j][c] = 0.0f;

    // stage K-slab kt (32 f32) into ring stage st: 2048 16B chunks, 8/thread
    auto stage = [&](int kt, int st) {
        #pragma unroll
        for (int i = 0; i < 8; i++) {
            const int id  = tid + (i << 8);
            const int arr = id >> 10;           // 0:A 1:B
            const int row = (id >> 3) & 127;
            const int c   = id & 7;
            const float* g = arr ? ga.B : ga.A;
            const int grow = (arr ? n0 : m0) + row;
            cp_async16(sbase + (uint32_t)st * G_STAGE + (uint32_t)arr * G_TILE
                           + (uint32_t)row * 128 + (uint32_t)((c ^ (row & 7)) << 4),
                       g + (size_t)grow * K + kt * 32 + c * 4);
        }
    };

    const int nk = K / 32;
    stage(0, 0);
    cp_commit();

    int st = 0, stn = 1;   // current stage, next stage
    for (int kt = 0; kt < nk; kt++) {
        const bool pf = (kt + 1) < nk;
        if (pf) { stage(kt + 1, stn); cp_commit(); }
        if (pf) cp_wait1(); else cp_wait0();
        __syncthreads();

        const uint32_t bb = sbase + (uint32_t)st * G_STAGE;
        #pragma unroll
        for (int kkg = 0; kkg < 4; kkg++) {
            const int c0 = (kkg << 1) + half;    // 16B chunk index (lane-dep)
            uint32_t Bf[4][2];
            #pragma unroll
            for (int pr = 0; pr < 2; pr++) {
                const int Rb = warp_n + pr * 16 + rowOff;
                uint32_t t[4];
                ldsm_x4(t, bb + G_TILE + (uint32_t)Rb * 128
                             + (uint32_t)((c0 ^ (Rb & 7)) << 4));
                Bf[pr*2][0] = t[0]; Bf[pr*2][1] = t[1];
                Bf[pr*2+1][0] = t[2]; Bf[pr*2+1][1] = t[3];
            }
            #pragma unroll
            for (int mt = 0; mt < 4; mt++) {
                const int Ra = warp_m + mt * 16 + rowOff;
                uint32_t t[4];
                ldsm_x4(t, bb + (uint32_t)Ra * 128
                             + (uint32_t)((c0 ^ (Ra & 7)) << 4));
                uint32_t af[4] = { t[0], t[2], t[1], t[3] };   // {a0,a1,a2,a3}
                #pragma unroll
                for (int nt = 0; nt < 4; nt++)
                    mma_tf32(acc[mt][nt], af, Bf[nt]);
            }
        }
        st = stn; stn = stn + 1; if (stn == 3) stn = 0;
    }

    // epilogue (D: c0,c1 row m cols 2tig..; c2,c3 row m+8)
    #pragma unroll
    for (int mt = 0; mt < 4; mt++) {
        const int m = m0 + warp_m + mt * 16 + gID;
        #pragma unroll
        for (int nt = 0; nt < 4; nt++) {
            const int n = n0 + warp_n + nt * 8 + 2 * tig;
            const float* c = acc[mt][nt];
            const float bv0 = ga.bias[n], bv1 = ga.bias[n + 1];
            float v00 = c[0] + bv0, v01 = c[1] + bv1;
            float v10 = c[2] + bv0, v11 = c[3] + bv1;
            if (fuse == 1) {
                v00 = to_tf32(fmaxf(v00, 0.0f)); v01 = to_tf32(fmaxf(v01, 0.0f));
                v10 = to_tf32(fmaxf(v10, 0.0f)); v11 = to_tf32(fmaxf(v11, 0.0f));
            } else if (fuse == 2) {
                float2 r0 = *(const float2*)(ga.res + (size_t)m * N + n);
                float2 r1 = *(const float2*)(ga.res + (size_t)(m + 8) * N + n);
                v00 += r0.x; v01 += r0.y; v10 += r1.x; v11 += r1.y;
            }
            *(float2*)(ga.Y + (size_t)m * N + n)       = make_float2(v00, v01);
            *(float2*)(ga.Y + (size_t)(m + 8) * N + n) = make_float2(v10, v11);
        }
    }
}

// ---------------------------------------------------------------------------
// Weight prep: W [K,N] f32 -> WT [N,K] f32 rna-rounded
__global__ __launch_bounds__(256) void transpose_round_kernel(
    const float* __restrict__ W, float* __restrict__ T, int K, int N)
{
    __shared__ float t[32][33];
    const int tx = threadIdx.x, ty = threadIdx.y;
    const int n0 = blockIdx.x * 32, k0 = blockIdx.y * 32;
    #pragma unroll
    for (int j = ty; j < 32; j += 8)
        t[j][tx] = W[(size_t)(k0 + j) * N + n0 + tx];
    __syncthreads();
    #pragma unroll
    for (int j = ty; j < 32; j += 8)
        T[(size_t)(n0 + j) * K + k0 + tx] = to_tf32(t[tx][j]);
}

// Elementwise rna round
__global__ void round_kernel(const float* __restrict__ X, float* __restrict__ Y, int n)
{
    int i = blockIdx.x * 256 + threadIdx.x;
    if (i < n) Y[i] = to_tf32(X[i]);
}

// ---------------------------------------------------------------------------
// LayerNorm over last dim (768); rna-rounded output (feeds GEMMs only).
__global__ __launch_bounds__(256) void layernorm_round_kernel(
    const float* __restrict__ X, const float* __restrict__ g,
    const float* __restrict__ be, float* __restrict__ Y)
{
    __shared__ float red[256];
    __shared__ float s_mean, s_inv;
    const int row = blockIdx.x, tid = threadIdx.x;
    const float* x = X + (size_t)row * Dsz;

    float s = 0.0f;
    for (int i = tid; i < Dsz; i += 256) s += x[i];
    red[tid] = s; __syncthreads();
    for (int o = 128; o > 0; o >>= 1) { if (tid < o) red[tid] += red[tid + o]; __syncthreads(); }
    if (tid == 0) s_mean = red[0] * (1.0f / Dsz);
    __syncthreads();
    const float m = s_mean;

    float v = 0.0f;
    for (int i = tid; i < Dsz; i += 256) { float d = x[i] - m; v += d * d; }
    red[tid] = v; __syncthreads();
    for (int o = 128; o > 0; o >>= 1) { if (tid < o) red[tid] += red[tid + o]; __syncthreads(); }
    if (tid == 0) s_inv = rsqrtf(red[0] * (1.0f / Dsz) + 1e-5f);
    __syncthreads();
    const float inv = s_inv;

    for (int i = tid; i < Dsz; i += 256)
        Y[(size_t)row * Dsz + i] = to_tf32((x[i] - m) * inv * g[i] + be[i]);
}

// ---------------------------------------------------------------------------
// Neighbor affinity (f32 qn/kn)
__global__ __launch_bounds__(128) void affinity_kernel(
    const float* __restrict__ qn, const float* __restrict__ kn,
    const float* __restrict__ prev, const int* __restrict__ lidx,
    float* __restrict__ a_out)
{
    const int t = blockIdx.x, b = blockIdx.y, tid = threadIdx.x;
    const float* q0 = qn + ((size_t)b * Ssz + t) * Dsz;
    const float* q1 = q0 + Dsz;
    const float* k0 = kn + ((size_t)b * Ssz + t) * Dsz;
    const float* k1 = k0 + Dsz;
    float sf = 0.0f, sb = 0.0f;
    for (int i = tid; i < Dsz; i += 128) { sf += q0[i] * k1[i]; sb += q1[i] * k0[i]; }
    __shared__ float rf[128], rb[128];
    rf[tid] = sf; rb[tid] = sb; __syncthreads();
    for (int o = 64; o > 0; o >>= 1) {
        if (tid < o) { rf[tid] += rf[tid + o]; rb[tid] += rb[tid + o]; }
        __syncthreads();
    }
    if (tid == 0) {
        float f = rf[0] * (1.0f / 64.0f), bw = rb[0] * (1.0f / 64.0f);
        float ah = 0.5f * (1.0f / (1.0f + expf(-f)) + 1.0f / (1.0f + expf(-bw)));
        float a;
        if (*lidx == 0) a = ah;
        else { float p = prev[(size_t)b * (Ssz - 1) + t]; a = p + (1.0f - p) * ah; }
        a_out[(size_t)b * (Ssz - 1) + t] = a;
    }
}

// L[b,0]=0; L[b,k]=sum_{t<k} log(a[b,t])
__global__ void scan_kernel(const float* __restrict__ a, float* __restrict__ Lout)
{
    const int b = blockIdx.x;
    if (threadIdx.x == 0) {
        float acc = 0.0f;
        Lout[(size_t)b * Ssz] = 0.0f;
        for (int t = 0; t < Ssz - 1; t++) {
            acc += logf(a[(size_t)b * (Ssz - 1) + t]);
            Lout[(size_t)b * Ssz + t + 1] = acc;
        }
    }
}

// ---------------------------------------------------------------------------
// Mask dtype handling
__global__ void mask_detect_kernel(const unsigned char* __restrict__ m)
{
    if (threadIdx.x == 0)
        g_mask_is_int = (m[1] == 0 && m[2] == 0 && m[3] == 0) ? 1 : 0;
}
__global__ void mask_norm_kernel(const void* __restrict__ m)
{
    int i = blockIdx.x * 256 + threadIdx.x;
    if (i < Bsz * Ssz) {
        int v = g_mask_is_int ? ((const int*)m)[i] : (int)((const unsigned char*)m)[i];
        g_mask[i] = v ? 1 : 0;
    }
}

// ---------------------------------------------------------------------------
// Fused attention; ctx written rna-rounded f32 (feeds Wo GEMM)
#define ATT_SC 0
#define ATT_QS 16512
#define ATT_KT 18592
#define ATT_LS 26912
#define ATT_MS 27424
#define ATT_SMEM_BYTES ((ATT_MS + 128) * 4)

__global__ __launch_bounds__(256) void attn_fused_kernel(
    const float* __restrict__ gq, const float* __restrict__ gk,
    const float* __restrict__ gv, const float* __restrict__ Lg,
    float* __restrict__ attnh, float* __restrict__ ctx)
{
    extern __shared__ float sm[];
    float* Sc = sm + ATT_SC;
    float* qs = sm + ATT_QS;
    float* kt = sm + ATT_KT;
    float* Ls = sm + ATT_LS;
    unsigned char* ms = (unsigned char*)(sm + ATT_MS);

    const int tid = threadIdx.x;
    const int bh = blockIdx.y, b = bh / Hsz, h = bh % Hsz;
    const int q0 = blockIdx.x * 32;

    for (int i = tid; i < Ssz; i += 256) {
        Ls[i] = Lg[(size_t)b * Ssz + i];
        ms[i] = g_mask[(size_t)b * Ssz + i];
    }
    {
        int r = tid >> 3, d8 = (tid & 7) << 3;
        const float* src = gq + ((size_t)b * Ssz + q0 + r) * Dsz + h * DHsz + d8;
        float* dst = qs + r * 65 + d8;
        #pragma unroll
        for (int u = 0; u < 8; u++) dst[u] = src[u];
    }
    __syncthreads();

    const int qg = tid >> 5;
    const int kg = tid & 31;

    for (int t = 0; t < 4; t++) {
        const int k0 = t * 128;
        {
            int krow = tid >> 1, dd = (tid & 1) << 5;
            const float* src = gk + ((size_t)b * Ssz + k0 + krow) * Dsz + h * DHsz + dd;
            float* dst = kt + krow * 65 + dd;
            #pragma unroll
            for (int u = 0; u < 32; u++) dst[u] = src[u];
        }
        __syncthreads();
        float acc[4][4] = {};
        #pragma unroll 4
        for (int dh = 0; dh < DHsz; dh++) {
            float qv[4], kv[4];
            #pragma unroll
            for (int i = 0; i < 4; i++) qv[i] = qs[(qg * 4 + i) * 65 + dh];
            #pragma unroll
            for (int j = 0; j < 4; j++) kv[j] = kt[(kg + 32 * j) * 65 + dh];
            #pragma unroll
            for (int i = 0; i < 4; i++)
                #pragma unroll
                for (int j = 0; j < 4; j++) acc[i][j] += qv[i] * kv[j];
        }
        #pragma unroll
        for (int i = 0; i < 4; i++)
            #pragma unroll
            for (int j = 0; j < 4; j++) {
                int kgl = k0 + kg + 32 * j;
                float vv = acc[i][j] * 0.125f;
                if (!ms[kgl]) vv = -1e9f;
                Sc[(qg * 4 + i) * 516 + kgl] = vv;
            }
        __syncthreads();
    }

    {
        const int row = tid >> 3, l8 = tid & 7;
        float* sr = Sc + row * 516;
        float mx = -1e30f;
        #pragma unroll 8
        for (int i = 0; i < 64; i++) mx = fmaxf(mx, sr[l8 + 8 * i]);
        for (int o = 1; o < 8; o <<= 1) mx = fmaxf(mx, __shfl_xor_sync(0xffffffffu, mx, o));
        float sum = 0.0f;
        #pragma unroll 8
        for (int i = 0; i < 64; i++) {
            int k = l8 + 8 * i;
            float e = __expf(sr[k] - mx);
            sr[k] = e; sum += e;
        }
        for (int o = 1; o < 8; o <<= 1) sum += __shfl_xor_sync(0xffffffffu, sum, o);
        const float inv = 1.0f / sum;
        const int qi = q0 + row;
        const float Lq = Ls[qi];
        #pragma unroll 8
        for (int i = 0; i < 64; i++) {
            int k = l8 + 8 * i;
            float Lk = Ls[k];
            float c = (qi >= k) ? __expf(Lq - Lk) : __expf(Lk - Lq);
            sr[k] = sr[k] * inv * c;
        }
    }
    __syncthreads();

    {
        float* dst = attnh + (size_t)bh * Ssz * Ssz + (size_t)q0 * Ssz;
        for (int idx = tid; idx < 32 * 512; idx += 256) {
            int r = idx >> 9, k = idx & 511;
            dst[(size_t)r * Ssz + k] = Sc[r * 516 + k];
        }
    }

    float oacc[2][4] = {};
    const int r0 = (tid >> 4) << 1;
    const int c0 = (tid & 15) << 2;
    for (int t = 0; t < 4; t++) {
        const int k0 = t * 128;
        __syncthreads();
        {
            int krow = tid >> 1, dd = (tid & 1) << 5;
            const float* src = gv + ((size_t)b * Ssz + k0 + krow) * Dsz + h * DHsz + dd;
            float* dst = kt + krow * 65 + dd;
            #pragma unroll
            for (int u = 0; u < 32; u++) dst[u] = src[u];
        }
        __syncthreads();
        #pragma unroll 4
        for (int kk = 0; kk < 128; kk++) {
            float a0 = Sc[r0 * 516 + k0 + kk];
            float a1 = Sc[(r0 + 1) * 516 + k0 + kk];
            const float* vr = kt + kk * 65 + c0;
            #pragma unroll
            for (int j = 0; j < 4; j++) { float bv = vr[j]; oacc[0][j] += a0 * bv; oacc[1][j] += a1 * bv; }
        }
    }
    #pragma unroll
    for (int rr = 0; rr < 2; rr++) {
        float4 o4 = make_float4(to_tf32(oacc[rr][0]), to_tf32(oacc[rr][1]),
                                to_tf32(oacc[rr][2]), to_tf32(oacc[rr][3]));
        *(float4*)(ctx + ((size_t)b * Ssz + q0 + r0 + rr) * Dsz + h * DHsz + c0) = o4;
    }
}

// ---------------------------------------------------------------------------
extern "C" void kernel_launch(void* const* d_in, const int* in_sizes, int n_in,
                              void* d_out, int out_size)
{
    (void)in_sizes; (void)n_in; (void)out_size;
    const float* x    = (const float*)d_in[0];
    const void*  mask = d_in[1];
    const float* prev = (const float*)d_in[2];
    const float* Wqn  = (const float*)d_in[3];  const float* bqn = (const float*)d_in[4];
    const float* Wkn  = (const float*)d_in[5];  const float* bkn = (const float*)d_in[6];
    const float* Wq   = (const float*)d_in[7];  const float* bq  = (const float*)d_in[8];
    const float* Wk   = (const float*)d_in[9];  const float* bk  = (const float*)d_in[10];
    const float* Wv   = (const float*)d_in[11]; const float* bv  = (const float*)d_in[12];
    const float* Wo   = (const float*)d_in[13]; const float* bo  = (const float*)d_in[14];
    const float* W1   = (const float*)d_in[15]; const float* b1  = (const float*)d_in[16];
    const float* W2   = (const float*)d_in[17]; const float* b2  = (const float*)d_in[18];
    const float* g1   = (const float*)d_in[19]; const float* be1 = (const float*)d_in[20];
    const float* g2   = (const float*)d_in[21]; const float* be2 = (const float*)d_in[22];
    const int*   lidx = (const int*)d_in[23];

    float* out_p   = (float*)d_out;
    float* a_p     = out_p + MDsz;
    float* attnh_p = a_p + (size_t)Bsz * (Ssz - 1);

    void* basep = nullptr;
    cudaGetSymbolAddress(&basep, g_f32);
    float* p = (float*)basep;
    float *qn = p;            p += MDsz;
    float *kn = p;            p += MDsz;
    float *qb = p;            p += MDsz;
    float *kb = p;            p += MDsz;
    float *vb = p;            p += MDsz;
    float *x1 = p;            p += MDsz;
    float *xn = p;            p += MDsz;
    float *xr = p;            p += MDsz;
    float *ctx = p;           p += MDsz;
    float *x2 = p;            p += MDsz;
    float *hid = p;           p += MFsz;
    float *WqnT = p;          p += DDsz;
    float *WknT = p;          p += DDsz;
    float *WqT = p;           p += DDsz;
    float *WkT = p;           p += DDsz;
    float *WvT = p;           p += DDsz;
    float *WoT = p;           p += DDsz;
    float *W1T = p;           p += DFsz;
    float *W2T = p;           p += DFsz;
    float *Lb = p;

    cudaFuncSetAttribute(attn_fused_kernel,
                         cudaFuncAttributeMaxDynamicSharedMemorySize, ATT_SMEM_BYTES);
    cudaFuncSetAttribute(gemm_tf32_ldsm_kernel,
                         cudaFuncAttributeMaxDynamicSharedMemorySize, G_SMEM);

    const dim3 tb(32, 8);
    const dim3 tD(Dsz / 32, Dsz / 32);
    const dim3 t1(FFsz / 32, Dsz / 32);     // W1 [D,FF] -> [FF,D]
    const dim3 t2(Dsz / 32, FFsz / 32);     // W2 [FF,D] -> [D,FF]

    // weight prep + producers
    transpose_round_kernel<<<tD, tb>>>(Wq, WqT, Dsz, Dsz);
    transpose_round_kernel<<<tD, tb>>>(Wk, WkT, Dsz, Dsz);
    transpose_round_kernel<<<tD, tb>>>(Wv, WvT, Dsz, Dsz);
    layernorm_round_kernel<<<MROWS, 256>>>(x, g1, be1, xn);
    round_kernel<<<(int)((MDsz + 255) / 256), 256>>>(x, xr, (int)MDsz);
    {
        GemmBatch gbat;
        gbat.a[0] = { xn, WqT, bq, nullptr, qb };
        gbat.a[1] = { xn, WkT, bk, nullptr, kb };
        gbat.a[2] = { xn, WvT, bv, nullptr, vb };
        gemm_tf32_ldsm_kernel<<<dim3(Dsz / 128, MROWS / 128, 3), 256, G_SMEM>>>(
            gbat, MROWS, Dsz, Dsz, 0);
    }
    transpose_round_kernel<<<tD, tb>>>(Wqn, WqnT, Dsz, Dsz);
    transpose_round_kernel<<<tD, tb>>>(Wkn, WknT, Dsz, Dsz);
    transpose_round_kernel<<<tD, tb>>>(Wo, WoT, Dsz, Dsz);
    transpose_round_kernel<<<t1, tb>>>(W1, W1T, Dsz, FFsz);
    transpose_round_kernel<<<t2, tb>>>(W2, W2T, FFsz, Dsz);
    mask_detect_kernel<<<1, 32>>>((const unsigned char*)mask);
    mask_norm_kernel<<<16, 256>>>(mask);

    // affinity path
    {
        GemmBatch gbat;
        gbat.a[0] = { xr, WqnT, bqn, nullptr, qn };
        gbat.a[1] = { xr, WknT, bkn, nullptr, kn };
        gbat.a[2] = gbat.a[0];
        gemm_tf32_ldsm_kernel<<<dim3(Dsz / 128, MROWS / 128, 2), 256, G_SMEM>>>(
            gbat, MROWS, Dsz, Dsz, 0);
    }
    affinity_kernel<<<dim3(Ssz - 1, Bsz), 128>>>(qn, kn, prev, lidx, a_p);
    scan_kernel<<<Bsz, 32>>>(a_p, Lb);

    // attention
    attn_fused_kernel<<<dim3(Ssz / 32, Bsz * Hsz), 256, ATT_SMEM_BYTES>>>(
        qb, kb, vb, Lb, attnh_p, ctx);

    // output proj + residual -> x1
    {
        GemmBatch gbat;
        gbat.a[0] = { ctx, WoT, bo, x, x1 };
        gbat.a[1] = gbat.a[0]; gbat.a[2] = gbat.a[0];
        gemm_tf32_ldsm_kernel<<<dim3(Dsz / 128, MROWS / 128, 1), 256, G_SMEM>>>(
            gbat, MROWS, Dsz, Dsz, 2);
    }
    layernorm_round_kernel<<<MROWS, 256>>>(x1, g2, be2, x2);
    // FFN1: relu + round
    {
        GemmBatch gbat;
        gbat.a[0] = { x2, W1T, b1, nullptr, hid };
        gbat.a[1] = gbat.a[0]; gbat.a[2] = gbat.a[0];
        gemm_tf32_ldsm_kernel<<<dim3(FFsz / 128, MROWS / 128, 1), 256, G_SMEM>>>(
            gbat, MROWS, FFsz, Dsz, 1);
    }
    // FFN2: + residual x1 -> out
    {
        GemmBatch gbat;
        gbat.a[0] = { hid, W2T, b2, x1, out_p };
        gbat.a[1] = gbat.a[0]; gbat.a[2] = gbat.a[0];
        gemm_tf32_ldsm_kernel<<<dim3(Dsz / 128, MROWS / 128, 1), 256, G_SMEM>>>(
            gbat, MROWS, Dsz, FFsz, 2);
    }
}

// round 17
// speedup vs baseline: 1.3148x; 1.1846x over previous
#include <cuda_runtime.h>
#include <math.h>
#include <stdint.h>

// Problem constants
#define Bsz 8
#define Ssz 512
#define Dsz 768
#define Hsz 12
#define DHsz 64
#define FFsz 3072
#define MROWS (Bsz*Ssz)   // 4096

// ---------------------------------------------------------------------------
// Scratch
#define MDsz ((size_t)MROWS*Dsz)
#define MFsz ((size_t)MROWS*FFsz)
#define DDsz ((size_t)Dsz*Dsz)
#define DFsz ((size_t)Dsz*FFsz)
#define F32_SCR (10*MDsz + MFsz + 6*DDsz + 2*DFsz + Bsz*Ssz)
static __device__ float g_f32[F32_SCR];
static __device__ unsigned char g_mask[Bsz*Ssz];
static __device__ int g_mask_is_int;

// ---------------------------------------------------------------------------
__device__ __forceinline__ uint32_t smem_u32(const void* p) {
    uint32_t a;
    asm("{ .reg .u64 t; cvta.to.shared.u64 t, %1; cvt.u32.u64 %0, t; }" : "=r"(a) : "l"(p));
    return a;
}
__device__ __forceinline__ float to_tf32(float x) {
    uint32_t u;
    asm("cvt.rna.tf32.f32 %0, %1;" : "=r"(u) : "f"(x));
    return __uint_as_float(u);
}
__device__ __forceinline__ void cp_async16(uint32_t saddr, const void* gptr) {
    asm volatile("cp.async.cg.shared.global [%0], [%1], 16;\n" :: "r"(saddr), "l"(gptr));
}
__device__ __forceinline__ void cp_commit() { asm volatile("cp.async.commit_group;\n"); }
__device__ __forceinline__ void cp_wait0() { asm volatile("cp.async.wait_group 0;\n"); }
__device__ __forceinline__ void cp_wait1() { asm volatile("cp.async.wait_group 1;\n"); }

__device__ __forceinline__ void ldsm_x4(uint32_t* r, uint32_t addr) {
    asm volatile("ldmatrix.sync.aligned.m8n8.x4.shared.b16 {%0,%1,%2,%3}, [%4];"
                 : "=r"(r[0]), "=r"(r[1]), "=r"(r[2]), "=r"(r[3]) : "r"(addr));
}
__device__ __forceinline__ void mma_tf32(float* c, const uint32_t* a, const uint32_t* b) {
    asm volatile(
        "mma.sync.aligned.m16n8k8.row.col.f32.tf32.tf32.f32 "
        "{%0,%1,%2,%3}, {%4,%5,%6,%7}, {%8,%9}, {%0,%1,%2,%3};\n"
        : "+f"(c[0]), "+f"(c[1]), "+f"(c[2]), "+f"(c[3])
        : "r"(a[0]), "r"(a[1]), "r"(a[2]), "r"(a[3]), "r"(b[0]), "r"(b[1]));
}

// ---------------------------------------------------------------------------
// tf32 single-pass GEMM (unchanged from R16: 3-stage ring, 2 CTAs/SM)
#define G_TILE  16384
#define G_STAGE 32768
#define G_SMEM  (3*G_STAGE)

struct GemmArgs { const float *A, *B, *bias, *res; float* Y; };
struct GemmBatch { GemmArgs a[5]; };

__global__ __launch_bounds__(256, 2) void gemm_tf32_ldsm_kernel(
    GemmBatch gb, int M, int N, int K, int fuse)
{
    const GemmArgs ga = gb.a[blockIdx.z];
    extern __shared__ unsigned char dsm[];
    const uint32_t sbase = smem_u32(dsm);

    const int tid = threadIdx.x, wid = tid >> 5, lane = tid & 31;
    const int gID = lane >> 2, tig = lane & 3;
    const int warp_m = (wid & 1) * 64, warp_n = (wid >> 1) * 32;
    const int m0 = blockIdx.y * 128, n0 = blockIdx.x * 128;

    const int q = lane >> 3, lrow = lane & 7;
    const int rowOff = ((q >> 1) << 3) + lrow;
    const int half   = q & 1;

    float acc[4][4][4];
    #pragma unroll
    for (int i = 0; i < 4; i++)
        #pragma unroll
        for (int j = 0; j < 4; j++)
            #pragma unroll
            for (int c = 0; c < 4; c++) acc[i][j][c] = 0.0f;

    auto stage = [&](int kt, int st) {
        #pragma unroll
        for (int i = 0; i < 8; i++) {
            const int id  = tid + (i << 8);
            const int arr = id >> 10;
            const int row = (id >> 3) & 127;
            const int c   = id & 7;
            const float* g = arr ? ga.B : ga.A;
            const int grow = (arr ? n0 : m0) + row;
            cp_async16(sbase + (uint32_t)st * G_STAGE + (uint32_t)arr * G_TILE
                           + (uint32_t)row * 128 + (uint32_t)((c ^ (row & 7)) << 4),
                       g + (size_t)grow * K + kt * 32 + c * 4);
        }
    };

    const int nk = K / 32;
    stage(0, 0);
    cp_commit();

    int st = 0, stn = 1;
    for (int kt = 0; kt < nk; kt++) {
        const bool pf = (kt + 1) < nk;
        if (pf) { stage(kt + 1, stn); cp_commit(); }
        if (pf) cp_wait1(); else cp_wait0();
        __syncthreads();

        const uint32_t bb = sbase + (uint32_t)st * G_STAGE;
        #pragma unroll
        for (int kkg = 0; kkg < 4; kkg++) {
            const int c0 = (kkg << 1) + half;
            uint32_t Bf[4][2];
            #pragma unroll
            for (int pr = 0; pr < 2; pr++) {
                const int Rb = warp_n + pr * 16 + rowOff;
                uint32_t t[4];
                ldsm_x4(t, bb + G_TILE + (uint32_t)Rb * 128
                             + (uint32_t)((c0 ^ (Rb & 7)) << 4));
                Bf[pr*2][0] = t[0]; Bf[pr*2][1] = t[1];
                Bf[pr*2+1][0] = t[2]; Bf[pr*2+1][1] = t[3];
            }
            #pragma unroll
            for (int mt = 0; mt < 4; mt++) {
                const int Ra = warp_m + mt * 16 + rowOff;
                uint32_t t[4];
                ldsm_x4(t, bb + (uint32_t)Ra * 128
                             + (uint32_t)((c0 ^ (Ra & 7)) << 4));
                uint32_t af[4] = { t[0], t[2], t[1], t[3] };
                #pragma unroll
                for (int nt = 0; nt < 4; nt++)
                    mma_tf32(acc[mt][nt], af, Bf[nt]);
            }
        }
        st = stn; stn = stn + 1; if (stn == 3) stn = 0;
    }

    #pragma unroll
    for (int mt = 0; mt < 4; mt++) {
        const int m = m0 + warp_m + mt * 16 + gID;
        #pragma unroll
        for (int nt = 0; nt < 4; nt++) {
            const int n = n0 + warp_n + nt * 8 + 2 * tig;
            const float* c = acc[mt][nt];
            const float bv0 = ga.bias[n], bv1 = ga.bias[n + 1];
            float v00 = c[0] + bv0, v01 = c[1] + bv1;
            float v10 = c[2] + bv0, v11 = c[3] + bv1;
            if (fuse == 1) {
                v00 = to_tf32(fmaxf(v00, 0.0f)); v01 = to_tf32(fmaxf(v01, 0.0f));
                v10 = to_tf32(fmaxf(v10, 0.0f)); v11 = to_tf32(fmaxf(v11, 0.0f));
            } else if (fuse == 2) {
                float2 r0 = *(const float2*)(ga.res + (size_t)m * N + n);
                float2 r1 = *(const float2*)(ga.res + (size_t)(m + 8) * N + n);
                v00 += r0.x; v01 += r0.y; v10 += r1.x; v11 += r1.y;
            }
            *(float2*)(ga.Y + (size_t)m * N + n)       = make_float2(v00, v01);
            *(float2*)(ga.Y + (size_t)(m + 8) * N + n) = make_float2(v10, v11);
        }
    }
}

// ---------------------------------------------------------------------------
// Weight prep / producers (unchanged)
__global__ __launch_bounds__(256) void transpose_round_kernel(
    const float* __restrict__ W, float* __restrict__ T, int K, int N)
{
    __shared__ float t[32][33];
    const int tx = threadIdx.x, ty = threadIdx.y;
    const int n0 = blockIdx.x * 32, k0 = blockIdx.y * 32;
    #pragma unroll
    for (int j = ty; j < 32; j += 8)
        t[j][tx] = W[(size_t)(k0 + j) * N + n0 + tx];
    __syncthreads();
    #pragma unroll
    for (int j = ty; j < 32; j += 8)
        T[(size_t)(n0 + j) * K + k0 + tx] = to_tf32(t[tx][j]);
}

__global__ void round_kernel(const float* __restrict__ X, float* __restrict__ Y, int n)
{
    int i = blockIdx.x * 256 + threadIdx.x;
    if (i < n) Y[i] = to_tf32(X[i]);
}

__global__ __launch_bounds__(256) void layernorm_round_kernel(
    const float* __restrict__ X, const float* __restrict__ g,
    const float* __restrict__ be, float* __restrict__ Y)
{
    __shared__ float red[256];
    __shared__ float s_mean, s_inv;
    const int row = blockIdx.x, tid = threadIdx.x;
    const float* x = X + (size_t)row * Dsz;

    float s = 0.0f;
    for (int i = tid; i < Dsz; i += 256) s += x[i];
    red[tid] = s; __syncthreads();
    for (int o = 128; o > 0; o >>= 1) { if (tid < o) red[tid] += red[tid + o]; __syncthreads(); }
    if (tid == 0) s_mean = red[0] * (1.0f / Dsz);
    __syncthreads();
    const float m = s_mean;

    float v = 0.0f;
    for (int i = tid; i < Dsz; i += 256) { float d = x[i] - m; v += d * d; }
    red[tid] = v; __syncthreads();
    for (int o = 128; o > 0; o >>= 1) { if (tid < o) red[tid] += red[tid + o]; __syncthreads(); }
    if (tid == 0) s_inv = rsqrtf(red[0] * (1.0f / Dsz) + 1e-5f);
    __syncthreads();
    const float inv = s_inv;

    for (int i = tid; i < Dsz; i += 256)
        Y[(size_t)row * Dsz + i] = to_tf32((x[i] - m) * inv * g[i] + be[i]);
}

__global__ __launch_bounds__(128) void affinity_kernel(
    const float* __restrict__ qn, const float* __restrict__ kn,
    const float* __restrict__ prev, const int* __restrict__ lidx,
    float* __restrict__ a_out)
{
    const int t = blockIdx.x, b = blockIdx.y, tid = threadIdx.x;
    const float* q0 = qn + ((size_t)b * Ssz + t) * Dsz;
    const float* q1 = q0 + Dsz;
    const float* k0 = kn + ((size_t)b * Ssz + t) * Dsz;
    const float* k1 = k0 + Dsz;
    float sf = 0.0f, sb = 0.0f;
    for (int i = tid; i < Dsz; i += 128) { sf += q0[i] * k1[i]; sb += q1[i] * k0[i]; }
    __shared__ float rf[128], rb[128];
    rf[tid] = sf; rb[tid] = sb; __syncthreads();
    for (int o = 64; o > 0; o >>= 1) {
        if (tid < o) { rf[tid] += rf[tid + o]; rb[tid] += rb[tid + o]; }
        __syncthreads();
    }
    if (tid == 0) {
        float f = rf[0] * (1.0f / 64.0f), bw = rb[0] * (1.0f / 64.0f);
        float ah = 0.5f * (1.0f / (1.0f + expf(-f)) + 1.0f / (1.0f + expf(-bw)));
        float a;
        if (*lidx == 0) a = ah;
        else { float p = prev[(size_t)b * (Ssz - 1) + t]; a = p + (1.0f - p) * ah; }
        a_out[(size_t)b * (Ssz - 1) + t] = a;
    }
}

__global__ void scan_kernel(const float* __restrict__ a, float* __restrict__ Lout)
{
    const int b = blockIdx.x;
    if (threadIdx.x == 0) {
        float acc = 0.0f;
        Lout[(size_t)b * Ssz] = 0.0f;
        for (int t = 0; t < Ssz - 1; t++) {
            acc += logf(a[(size_t)b * (Ssz - 1) + t]);
            Lout[(size_t)b * Ssz + t + 1] = acc;
        }
    }
}

__global__ void mask_detect_kernel(const unsigned char* __restrict__ m)
{
    if (threadIdx.x == 0)
        g_mask_is_int = (m[1] == 0 && m[2] == 0 && m[3] == 0) ? 1 : 0;
}
__global__ void mask_norm_kernel(const void* __restrict__ m)
{
    int i = blockIdx.x * 256 + threadIdx.x;
    if (i < Bsz * Ssz) {
        int v = g_mask_is_int ? ((const int*)m)[i] : (int)((const unsigned char*)m)[i];
        g_mask[i] = v ? 1 : 0;
    }
}

// ---------------------------------------------------------------------------
// Fused attention v2: scores AND ctx on tf32 HMMA.
// smem (floats): Sc[32][516] @0 | qs[32][68] @16512 | kt[128][68]/vt[64][132] @18688
//                | Ls[512] @27392 | ms(512B) @27904
#define ATT_SC 0
#define ATT_QS 16512
#define ATT_KT 18688
#define ATT_LS 27392
#define ATT_MS 27904
#define ATT_SMEM_BYTES ((ATT_MS + 160) * 4)

__global__ __launch_bounds__(256) void attn_fused_kernel(
    const float* __restrict__ gq, const float* __restrict__ gk,
    const float* __restrict__ gv, const float* __restrict__ Lg,
    float* __restrict__ attnh, float* __restrict__ ctx)
{
    extern __shared__ float sm[];
    float* Sc = sm + ATT_SC;
    float* qs = sm + ATT_QS;
    float* kt = sm + ATT_KT;
    float* vt = sm + ATT_KT;                      // union with kt
    float* Ls = sm + ATT_LS;
    unsigned char* ms = (unsigned char*)(sm + ATT_MS);

    const uint32_t sb_sc = smem_u32(Sc);
    const uint32_t sb_qs = smem_u32(qs);
    const uint32_t sb_kt = smem_u32(kt);

    const int tid = threadIdx.x, wid = tid >> 5, lane = tid & 31;
    const int gID = lane >> 2, tig = lane & 3;
    const int bh = blockIdx.y, b = bh / Hsz, h = bh % Hsz;
    const int q0 = blockIdx.x * 32;

    // verified ldmatrix lane constants (identical to GEMM)
    const int qq = lane >> 3, lrow = lane & 7;
    const int rowOff = ((qq >> 1) << 3) + lrow;
    const int half   = qq & 1;

    for (int i = tid; i < Ssz; i += 256) {
        Ls[i] = Lg[(size_t)b * Ssz + i];
        ms[i] = g_mask[(size_t)b * Ssz + i];
    }
    {   // Q tile 32x64 -> qs stride 68
        int r = tid >> 3, d8 = (tid & 7) << 3;
        const float* src = gq + ((size_t)b * Ssz + q0 + r) * Dsz + h * DHsz + d8;
        float* dst = qs + r * 68 + d8;
        #pragma unroll
        for (int u = 0; u < 8; u++) dst[u] = src[u];
    }

    // ---- phase 1: scores via mma; 4 k0-tiles of 128 ----
    const int n0w = wid * 16;                     // warp's 16 cols within tile
    for (int t = 0; t < 4; t++) {
        const int k0 = t * 128;
        __syncthreads();                          // protect kt reuse + first-iter preamble
        {
            int krow = tid >> 1, dd = (tid & 1) << 5;
            const float* src = gk + ((size_t)b * Ssz + k0 + krow) * Dsz + h * DHsz + dd;
            float* dst = kt + krow * 68 + dd;
            #pragma unroll
            for (int u = 0; u < 32; u++) dst[u] = src[u];
        }
        __syncthreads();

        float acc[2][2][4];
        #pragma unroll
        for (int i = 0; i < 2; i++)
            #pragma unroll
            for (int j = 0; j < 2; j++)
                #pragma unroll
                for (int c = 0; c < 4; c++) acc[i][j][c] = 0.0f;

        #pragma unroll
        for (int kk = 0; kk < 8; kk++) {
            const int c0 = (kk << 1) + half;
            uint32_t Bf[2][2];
            {
                const int Rb = n0w + rowOff;
                uint32_t tt[4];
                ldsm_x4(tt, sb_kt + (uint32_t)(Rb * 272 + c0 * 16));
                Bf[0][0] = tt[0]; Bf[0][1] = tt[1];
                Bf[1][0] = tt[2]; Bf[1][1] = tt[3];
            }
            #pragma unroll
            for (int mt = 0; mt < 2; mt++) {
                const int Ra = mt * 16 + rowOff;
                uint32_t tt[4];
                ldsm_x4(tt, sb_qs + (uint32_t)(Ra * 272 + c0 * 16));
                uint32_t af[4] = { tt[0], tt[2], tt[1], tt[3] };
                mma_tf32(acc[mt][0], af, Bf[0]);
                mma_tf32(acc[mt][1], af, Bf[1]);
            }
        }
        // scatter to Sc with scale + mask
        #pragma unroll
        for (int mt = 0; mt < 2; mt++) {
            #pragma unroll
            for (int nt = 0; nt < 2; nt++) {
                const int col = k0 + n0w + nt * 8 + 2 * tig;
                const float* c = acc[mt][nt];
                const int r0r = mt * 16 + gID;
                float v00 = c[0] * 0.125f, v01 = c[1] * 0.125f;
                float v10 = c[2] * 0.125f, v11 = c[3] * 0.125f;
                if (!ms[col])     { v00 = -1e9f; v10 = -1e9f; }
                if (!ms[col + 1]) { v01 = -1e9f; v11 = -1e9f; }
                Sc[r0r * 516 + col]           = v00;
                Sc[r0r * 516 + col + 1]       = v01;
                Sc[(r0r + 8) * 516 + col]     = v10;
                Sc[(r0r + 8) * 516 + col + 1] = v11;
            }
        }
    }
    __syncthreads();

    // ---- phase 2: softmax + hierarchical C ----
    {
        const int row = tid >> 3, l8 = tid & 7;
        float* sr = Sc + row * 516;
        float mx = -1e30f;
        #pragma unroll 8
        for (int i = 0; i < 64; i++) mx = fmaxf(mx, sr[l8 + 8 * i]);
        for (int o = 1; o < 8; o <<= 1) mx = fmaxf(mx, __shfl_xor_sync(0xffffffffu, mx, o));
        float sum = 0.0f;
        #pragma unroll 8
        for (int i = 0; i < 64; i++) {
            int k = l8 + 8 * i;
            float e = __expf(sr[k] - mx);
            sr[k] = e; sum += e;
        }
        for (int o = 1; o < 8; o <<= 1) sum += __shfl_xor_sync(0xffffffffu, sum, o);
        const float inv = 1.0f / sum;
        const int qi = q0 + row;
        const float Lq = Ls[qi];
        #pragma unroll 8
        for (int i = 0; i < 64; i++) {
            int k = l8 + 8 * i;
            float Lk = Ls[k];
            float c = (qi >= k) ? __expf(Lq - Lk) : __expf(Lk - Lq);
            sr[k] = sr[k] * inv * c;
        }
    }
    __syncthreads();

    // ---- write attn_h (exact) and round Sc in place for ctx mma ----
    {
        float* dst = attnh + (size_t)bh * Ssz * Ssz + (size_t)q0 * Ssz;
        for (int idx = tid; idx < 32 * 512; idx += 256) {
            int r = idx >> 9, k = idx & 511;
            float v = Sc[r * 516 + k];
            dst[(size_t)r * Ssz + k] = v;
            Sc[r * 516 + k] = to_tf32(v);
        }
    }

    // ---- phase 3: ctx = P @ V via mma ----
    const int mtw = wid & 1;                 // warp's m-tile
    const int nbw = (wid >> 1) * 16;         // warp's 16 dh cols
    float oacc[2][4] = {};
    for (int t = 0; t < 4; t++) {
        const int k0 = t * 128;
        __syncthreads();                     // protect vt reuse (and Sc rounding on t=0)
        {   // stage V transposed: vt[dh][krow], stride 132
            int krow = tid >> 1, dhh = (tid & 1) << 5;
            const float* src = gv + ((size_t)b * Ssz + k0 + krow) * Dsz + h * DHsz + dhh;
            #pragma unroll
            for (int u = 0; u < 32; u++) vt[(dhh + u) * 132 + krow] = src[u];
        }
        __syncthreads();

        #pragma unroll
        for (int kk = 0; kk < 16; kk++) {
            const int c0 = (kk << 1) + half;
            uint32_t Bf[2][2];
            {
                const int Rb = nbw + rowOff;
                uint32_t tt[4];
                ldsm_x4(tt, sb_kt + (uint32_t)(Rb * 528 + c0 * 16));
                Bf[0][0] = tt[0]; Bf[0][1] = tt[1];
                Bf[1][0] = tt[2]; Bf[1][1] = tt[3];
            }
            const int Ra = mtw * 16 + rowOff;
            uint32_t tt[4];
            ldsm_x4(tt, sb_sc + (uint32_t)(Ra * 2064 + ((k0 >> 2) + c0) * 16));
            uint32_t af[4] = { tt[0], tt[2], tt[1], tt[3] };
            mma_tf32(oacc[0], af, Bf[0]);
            mma_tf32(oacc[1], af, Bf[1]);
        }
    }
    // ctx epilogue: rounded f32 (feeds Wo GEMM)
    #pragma unroll
    for (int nt = 0; nt < 2; nt++) {
        const int m = q0 + mtw * 16 + gID;
        const int n = h * DHsz + nbw + nt * 8 + 2 * tig;
        const float* c = oacc[nt];
        *(float2*)(ctx + ((size_t)b * Ssz + m) * Dsz + n) =
            make_float2(to_tf32(c[0]), to_tf32(c[1]));
        *(float2*)(ctx + ((size_t)b * Ssz + m + 8) * Dsz + n) =
            make_float2(to_tf32(c[2]), to_tf32(c[3]));
    }
}

// ---------------------------------------------------------------------------
extern "C" void kernel_launch(void* const* d_in, const int* in_sizes, int n_in,
                              void* d_out, int out_size)
{
    (void)in_sizes; (void)n_in; (void)out_size;
    const float* x    = (const float*)d_in[0];
    const void*  mask = d_in[1];
    const float* prev = (const float*)d_in[2];
    const float* Wqn  = (const float*)d_in[3];  const float* bqn = (const float*)d_in[4];
    const float* Wkn  = (const float*)d_in[5];  const float* bkn = (const float*)d_in[6];
    const float* Wq   = (const float*)d_in[7];  const float* bq  = (const float*)d_in[8];
    const float* Wk   = (const float*)d_in[9];  const float* bk  = (const float*)d_in[10];
    const float* Wv   = (const float*)d_in[11]; const float* bv  = (const float*)d_in[12];
    const float* Wo   = (const float*)d_in[13]; const float* bo  = (const float*)d_in[14];
    const float* W1   = (const float*)d_in[15]; const float* b1  = (const float*)d_in[16];
    const float* W2   = (const float*)d_in[17]; const float* b2  = (const float*)d_in[18];
    const float* g1   = (const float*)d_in[19]; const float* be1 = (const float*)d_in[20];
    const float* g2   = (const float*)d_in[21]; const float* be2 = (const float*)d_in[22];
    const int*   lidx = (const int*)d_in[23];

    float* out_p   = (float*)d_out;
    float* a_p     = out_p + MDsz;
    float* attnh_p = a_p + (size_t)Bsz * (Ssz - 1);

    void* basep = nullptr;
    cudaGetSymbolAddress(&basep, g_f32);
    float* p = (float*)basep;
    float *qn = p;            p += MDsz;
    float *kn = p;            p += MDsz;
    float *qb = p;            p += MDsz;
    float *kb = p;            p += MDsz;
    float *vb = p;            p += MDsz;
    float *x1 = p;            p += MDsz;
    float *xn = p;            p += MDsz;
    float *xr = p;            p += MDsz;
    float *ctx = p;           p += MDsz;
    float *x2 = p;            p += MDsz;
    float *hid = p;           p += MFsz;
    float *WqnT = p;          p += DDsz;
    float *WknT = p;          p += DDsz;
    float *WqT = p;           p += DDsz;
    float *WkT = p;           p += DDsz;
    float *WvT = p;           p += DDsz;
    float *WoT = p;           p += DDsz;
    float *W1T = p;           p += DFsz;
    float *W2T = p;           p += DFsz;
    float *Lb = p;

    cudaFuncSetAttribute(attn_fused_kernel,
                         cudaFuncAttributeMaxDynamicSharedMemorySize, ATT_SMEM_BYTES);
    cudaFuncSetAttribute(gemm_tf32_ldsm_kernel,
                         cudaFuncAttributeMaxDynamicSharedMemorySize, G_SMEM);

    const dim3 tb(32, 8);
    const dim3 tD(Dsz / 32, Dsz / 32);
    const dim3 t1(FFsz / 32, Dsz / 32);
    const dim3 t2(Dsz / 32, FFsz / 32);

    // weight prep + producers for the merged 5-way GEMM
    transpose_round_kernel<<<tD, tb>>>(Wq, WqT, Dsz, Dsz);
    transpose_round_kernel<<<tD, tb>>>(Wk, WkT, Dsz, Dsz);
    transpose_round_kernel<<<tD, tb>>>(Wv, WvT, Dsz, Dsz);
    transpose_round_kernel<<<tD, tb>>>(Wqn, WqnT, Dsz, Dsz);
    transpose_round_kernel<<<tD, tb>>>(Wkn, WknT, Dsz, Dsz);
    layernorm_round_kernel<<<MROWS, 256>>>(x, g1, be1, xn);
    round_kernel<<<(int)((MDsz + 255) / 256), 256>>>(x, xr, (int)MDsz);

    // merged QKV + qn/kn GEMM (z=5, 960 CTAs)
    {
        GemmBatch gbat;
        gbat.a[0] = { xn, WqT, bq, nullptr, qb };
        gbat.a[1] = { xn, WkT, bk, nullptr, kb };
        gbat.a[2] = { xn, WvT, bv, nullptr, vb };
        gbat.a[3] = { xr, WqnT, bqn, nullptr, qn };
        gbat.a[4] = { xr, WknT, bkn, nullptr, kn };
        gemm_tf32_ldsm_kernel<<<dim3(Dsz / 128, MROWS / 128, 5), 256, G_SMEM>>>(
            gbat, MROWS, Dsz, Dsz, 0);
    }
    transpose_round_kernel<<<tD, tb>>>(Wo, WoT, Dsz, Dsz);
    transpose_round_kernel<<<t1, tb>>>(W1, W1T, Dsz, FFsz);
    transpose_round_kernel<<<t2, tb>>>(W2, W2T, FFsz, Dsz);
    mask_detect_kernel<<<1, 32>>>((const unsigned char*)mask);
    mask_norm_kernel<<<16, 256>>>(mask);

    affinity_kernel<<<dim3(Ssz - 1, Bsz), 128>>>(qn, kn, prev, lidx, a_p);
    scan_kernel<<<Bsz, 32>>>(a_p, Lb);

    // attention (both matmuls on HMMA)
    attn_fused_kernel<<<dim3(Ssz / 32, Bsz * Hsz), 256, ATT_SMEM_BYTES>>>(
        qb, kb, vb, Lb, attnh_p, ctx);

    // output proj + residual -> x1
    {
        GemmBatch gbat;
        gbat.a[0] = { ctx, WoT, bo, x, x1 };
        gemm_tf32_ldsm_kernel<<<dim3(Dsz / 128, MROWS / 128, 1), 256, G_SMEM>>>(
            gbat, MROWS, Dsz, Dsz, 2);
    }
    layernorm_round_kernel<<<MROWS, 256>>>(x1, g2, be2, x2);
    // FFN1: relu + round
    {
        GemmBatch gbat;
        gbat.a[0] = { x2, W1T, b1, nullptr, hid };
        gemm_tf32_ldsm_kernel<<<dim3(FFsz / 128, MROWS / 128, 1), 256, G_SMEM>>>(
            gbat, MROWS, FFsz, Dsz, 1);
    }
    // FFN2: + residual x1 -> out
    {
        GemmBatch gbat;
        gbat.a[0] = { hid, W2T, b2, x1, out_p };
        gemm_tf32_ldsm_kernel<<<dim3(Dsz / 128, MROWS / 128, 1), 256, G_SMEM>>>(
            gbat, MROWS, Dsz, FFsz, 2);
    }
}